// round 10
// baseline (speedup 1.0000x reference)
#include <cuda_runtime.h>
#include <math.h>
#include <stdint.h>

#define NUSERS 50000
#define NITEMS 20000
#define NNODES 70000
#define FDIM   768
#define H1D    512
#define HID    128
#define NEDGE  2000000
#define ALPHA  0.25f
#define LN_EPS 1e-5f

#define SCAN_B 512
#define SCAN_G ((NNODES + SCAN_B - 1) / SCAN_B)   // 137

// ---------------- scratch ----------------
__device__ float g_t1[(size_t)NITEMS * H1D];
__device__ float g_t2[(size_t)NITEMS * HID];
__device__ float g_t3[(size_t)NITEMS * HID];
__device__ float g_xa[(size_t)NNODES * HID];
__device__ float g_xb[(size_t)NNODES * HID];
__device__ float g_dinv[NNODES];
__device__ int   g_deg[NNODES];
__device__ int   g_cur[NNODES];
__device__ int   g_offs[NNODES + 1];
__device__ int   g_bsum[SCAN_G];
__device__ int   g_boff[SCAN_G];
__device__ int   g_csrc[NEDGE];
__device__ float g_cw[NEDGE];

// ---------------- packed f32x2 SGEMM: C = A[M,K]@B[K,N] + bias ---------------
// BM=BN=128, BK=16, 256 threads, 8x8 per thread.
// A staged DUPLICATED ({a,a} pairs) so fma.rn.f32x2 (Blackwell packed fp32 FMA,
// 2 full-precision MACs/instr) can pair output columns. Bitwise identical math
// to scalar FFMA at ~2x the MAC rate.
#define ASTR 260   // dup-A row stride (floats); %4==0 for 16B loads
#define BSTR 132   // B row stride (floats)
__global__ __launch_bounds__(256) void sgemm_f32x2(const float* __restrict__ A,
                                                   const float* __restrict__ B,
                                                   const float* __restrict__ bias,
                                                   float* __restrict__ C,
                                                   int M, int N, int K)
{
    __shared__ float Asd[16 * ASTR];   // [k][2*m] duplicated pairs
    __shared__ float Bs[16 * BSTR];    // [k][n]

    int tid = threadIdx.x;
    int tx = tid & 15;        // column group: owns cols tx*2 + jp*32
    int ty = tid >> 4;        // row group:    owns rows ty*8 + i
    int row0 = blockIdx.y * 128;
    int col0 = blockIdx.x * 128;

    unsigned long long acc[8][4];
#pragma unroll
    for (int i = 0; i < 8; i++)
#pragma unroll
        for (int jp = 0; jp < 4; jp++) acc[i][jp] = 0ull;   // {0.f,0.f}

    for (int k0 = 0; k0 < K; k0 += 16) {
#pragma unroll
        for (int it = 0; it < 2; ++it) {
            int idx = tid + it * 256;                 // 0..511
            // A tile: 128 rows x 16 k, stored k-major duplicated
            int ar = idx >> 2, ac = (idx & 3) * 4;
            int gr = row0 + ar;
            float4 av = make_float4(0.f, 0.f, 0.f, 0.f);
            if (gr < M) av = *(const float4*)(A + (size_t)gr * K + k0 + ac);
            *(float2*)&Asd[(ac + 0) * ASTR + 2 * ar] = make_float2(av.x, av.x);
            *(float2*)&Asd[(ac + 1) * ASTR + 2 * ar] = make_float2(av.y, av.y);
            *(float2*)&Asd[(ac + 2) * ASTR + 2 * ar] = make_float2(av.z, av.z);
            *(float2*)&Asd[(ac + 3) * ASTR + 2 * ar] = make_float2(av.w, av.w);
            // B tile: 16 rows x 128 cols
            int br = idx >> 5, bc = (idx & 31) * 4;
            float4 bv = *(const float4*)(B + (size_t)(k0 + br) * N + col0 + bc);
            *(float4*)&Bs[br * BSTR + bc] = bv;
        }
        __syncthreads();

#pragma unroll
        for (int k = 0; k < 16; k++) {
            unsigned long long ad[8];
#pragma unroll
            for (int q = 0; q < 4; q++) {            // 128-bit loads, 2 dup-pairs each
                ulonglong2 t = *(const ulonglong2*)&Asd[k * ASTR + ty * 16 + q * 4];
                ad[2 * q] = t.x; ad[2 * q + 1] = t.y;
            }
            unsigned long long bd[4];
#pragma unroll
            for (int jp = 0; jp < 4; jp++)           // 16 consecutive 8B addrs/warp: conflict-free
                bd[jp] = *(const unsigned long long*)&Bs[k * BSTR + jp * 32 + tx * 2];
#pragma unroll
            for (int i = 0; i < 8; i++)
#pragma unroll
                for (int jp = 0; jp < 4; jp++)
                    asm("fma.rn.f32x2 %0, %1, %2, %0;"
                        : "+l"(acc[i][jp]) : "l"(ad[i]), "l"(bd[jp]));
        }
        __syncthreads();
    }

    // epilogue: += bias, guarded rows
#pragma unroll
    for (int i = 0; i < 8; i++) {
        int gr = row0 + ty * 8 + i;
        if (gr >= M) continue;
#pragma unroll
        for (int jp = 0; jp < 4; jp++) {
            int gc = col0 + jp * 32 + tx * 2;
            float2 p = *(float2*)&acc[i][jp];
            p.x += bias[gc];
            p.y += bias[gc + 1];
            *(float2*)(C + (size_t)gr * N + gc) = p;
        }
    }
}

// ---------------- LayerNorm + ReLU ----------------
template <int W>
__global__ void ln_relu(float* __restrict__ x, const float* __restrict__ g,
                        const float* __restrict__ be)
{
    constexpr int VPT = W / 128;
    int row = blockIdx.x;
    int tid = threadIdx.x;
    float* xr = x + (size_t)row * W;

    float v[VPT];
    float s = 0.f, s2 = 0.f;
#pragma unroll
    for (int i = 0; i < VPT; i++) {
        v[i] = xr[i * 128 + tid];
        s += v[i]; s2 += v[i] * v[i];
    }
#pragma unroll
    for (int o = 16; o > 0; o >>= 1) {
        s  += __shfl_xor_sync(0xffffffffu, s,  o);
        s2 += __shfl_xor_sync(0xffffffffu, s2, o);
    }
    __shared__ float rs[4], rs2[4];
    if ((tid & 31) == 0) { rs[tid >> 5] = s; rs2[tid >> 5] = s2; }
    __syncthreads();
    s  = rs[0] + rs[1] + rs[2] + rs[3];
    s2 = rs2[0] + rs2[1] + rs2[2] + rs2[3];

    float mu  = s / W;
    float var = s2 / W - mu * mu;
    float inv = rsqrtf(var + LN_EPS);
#pragma unroll
    for (int i = 0; i < VPT; i++) {
        int c = i * 128 + tid;
        float y = (v[i] - mu) * inv * g[c] + be[c];
        xr[c] = fmaxf(y, 0.f);
    }
}

// ---------------- build e0 ----------------
__global__ void build_e0(const float* __restrict__ emb, const float* __restrict__ mw,
                         float* __restrict__ out)
{
    int node = blockIdx.x;
    int tid = threadIdx.x;   // 128
    float x = emb[(size_t)node * HID + tid];
    if (node >= NUSERS) {
        int it = node - NUSERS;
        float h = g_t3[(size_t)it * HID + tid];
        float s2 = h * h;
#pragma unroll
        for (int o = 16; o > 0; o >>= 1) s2 += __shfl_xor_sync(0xffffffffu, s2, o);
        __shared__ float red[4];
        if ((tid & 31) == 0) red[tid >> 5] = s2;
        __syncthreads();
        float nrm = sqrtf(red[0] + red[1] + red[2] + red[3]);
        x += mw[0] * h / fmaxf(nrm, 1e-12f);
    }
    size_t o = (size_t)node * HID + tid;
    g_xa[o] = x;
    out[o] = ALPHA * x;
}

// ---------------- degree / dinv ----------------
__global__ void zero_deg_cur()
{
    int n = blockIdx.x * blockDim.x + threadIdx.x;
    if (n < NNODES) { g_deg[n] = 0; g_cur[n] = 0; }
}

__global__ void deg_count(const int* __restrict__ dst)
{
    int e = blockIdx.x * blockDim.x + threadIdx.x;
    if (e < NEDGE) atomicAdd(&g_deg[dst[e]], 1);
}

__global__ void dinv_k()
{
    int n = blockIdx.x * blockDim.x + threadIdx.x;
    if (n < NNODES) {
        int d = g_deg[n];
        g_dinv[n] = (d > 0) ? rsqrtf((float)d) : 0.f;
    }
}

// ---------------- exclusive scan of g_deg -> g_offs ----------------
__global__ void scan1()
{
    __shared__ int sm[SCAN_B];
    int i = blockIdx.x * SCAN_B + threadIdx.x;
    int v = (i < NNODES) ? g_deg[i] : 0;
    sm[threadIdx.x] = v;
    __syncthreads();
    int val = v;
#pragma unroll
    for (int o = 1; o < SCAN_B; o <<= 1) {
        int t = (threadIdx.x >= o) ? sm[threadIdx.x - o] : 0;
        __syncthreads();
        val += t;
        sm[threadIdx.x] = val;
        __syncthreads();
    }
    if (i < NNODES) g_offs[i] = val - v;
    if (threadIdx.x == SCAN_B - 1) g_bsum[blockIdx.x] = val;
}

__global__ void scan2()
{
    __shared__ int sm[SCAN_G];
    int t = threadIdx.x;
    int v = (t < SCAN_G) ? g_bsum[t] : 0;
    if (t < SCAN_G) sm[t] = v;
    __syncthreads();
    if (t < SCAN_G) {
        int e = 0;
        for (int j = 0; j < t; j++) e += sm[j];
        g_boff[t] = e;
    }
}

__global__ void scan3()
{
    int i = blockIdx.x * blockDim.x + threadIdx.x;
    if (i < NNODES) g_offs[i] += g_boff[i / SCAN_B];
    if (i == 0) g_offs[NNODES] = NEDGE;
}

// ---------------- scatter edges into CSR (by dst) ----------------
__global__ void scatter_edges(const int* __restrict__ src, const int* __restrict__ dst)
{
    int e = blockIdx.x * blockDim.x + threadIdx.x;
    if (e < NEDGE) {
        int s = src[e];
        int d = dst[e];
        int pos = g_offs[d] + atomicAdd(&g_cur[d], 1);
        g_csrc[pos] = s;
        g_cw[pos] = g_dinv[s];
    }
}

// ---------------- CSR propagate, fused out += alpha * xnew -------------------
__global__ void propagate_csr(const float* __restrict__ xin, float* __restrict__ xout,
                              float* __restrict__ out)
{
    int node = (blockIdx.x * blockDim.x + threadIdx.x) >> 5;
    int lane = threadIdx.x & 31;
    if (node >= NNODES) return;
    int beg = g_offs[node];
    int end = g_offs[node + 1];

    float4 acc = make_float4(0.f, 0.f, 0.f, 0.f);
    int j = beg;
    for (; j + 3 < end; j += 4) {
        int   s0 = __ldg(&g_csrc[j]),     s1 = __ldg(&g_csrc[j + 1]);
        int   s2 = __ldg(&g_csrc[j + 2]), s3 = __ldg(&g_csrc[j + 3]);
        float w0 = __ldg(&g_cw[j]),       w1 = __ldg(&g_cw[j + 1]);
        float w2 = __ldg(&g_cw[j + 2]),   w3 = __ldg(&g_cw[j + 3]);
        float4 v0 = *(const float4*)(xin + (size_t)s0 * HID + lane * 4);
        float4 v1 = *(const float4*)(xin + (size_t)s1 * HID + lane * 4);
        float4 v2 = *(const float4*)(xin + (size_t)s2 * HID + lane * 4);
        float4 v3 = *(const float4*)(xin + (size_t)s3 * HID + lane * 4);
        acc.x += w0 * v0.x + w1 * v1.x + w2 * v2.x + w3 * v3.x;
        acc.y += w0 * v0.y + w1 * v1.y + w2 * v2.y + w3 * v3.y;
        acc.z += w0 * v0.z + w1 * v1.z + w2 * v2.z + w3 * v3.z;
        acc.w += w0 * v0.w + w1 * v1.w + w2 * v2.w + w3 * v3.w;
    }
    for (; j < end; ++j) {
        int   s = __ldg(&g_csrc[j]);
        float w = __ldg(&g_cw[j]);
        float4 v = *(const float4*)(xin + (size_t)s * HID + lane * 4);
        acc.x += w * v.x; acc.y += w * v.y; acc.z += w * v.z; acc.w += w * v.w;
    }

    float dn = g_dinv[node];
    acc.x *= dn; acc.y *= dn; acc.z *= dn; acc.w *= dn;

    size_t o = (size_t)node * HID + lane * 4;
    *(float4*)(xout + o) = acc;
    float4 ov = *(float4*)(out + o);
    ov.x += ALPHA * acc.x; ov.y += ALPHA * acc.y;
    ov.z += ALPHA * acc.z; ov.w += ALPHA * acc.w;
    *(float4*)(out + o) = ov;
}

// ---------------- launch ----------------
extern "C" void kernel_launch(void* const* d_in, const int* in_sizes, int n_in,
                              void* d_out, int out_size)
{
    const int*   eidx = (const int*)d_in[0];
    const float* feat = (const float*)d_in[1];
    const float* emb  = (const float*)d_in[2];
    const float* W1   = (const float*)d_in[3];
    const float* b1   = (const float*)d_in[4];
    const float* gm1  = (const float*)d_in[5];
    const float* be1  = (const float*)d_in[6];
    const float* W2   = (const float*)d_in[7];
    const float* b2   = (const float*)d_in[8];
    const float* gm2  = (const float*)d_in[9];
    const float* be2  = (const float*)d_in[10];
    const float* W3   = (const float*)d_in[11];
    const float* b3   = (const float*)d_in[12];
    const float* mw   = (const float*)d_in[13];
    float* out = (float*)d_out;

    const int* src = eidx;
    const int* dst = eidx + NEDGE;

    float *t1, *t2, *t3, *xa, *xb;
    cudaGetSymbolAddress((void**)&t1, g_t1);
    cudaGetSymbolAddress((void**)&t2, g_t2);
    cudaGetSymbolAddress((void**)&t3, g_t3);
    cudaGetSymbolAddress((void**)&xa, g_xa);
    cudaGetSymbolAddress((void**)&xb, g_xb);

    const int MROWS = (NITEMS + 127) / 128;   // 157

    // ---- item metadata MLP (packed-f32x2 GEMMs) ----
    sgemm_f32x2<<<dim3(H1D / 128, MROWS), 256>>>(feat, W1, b1, t1, NITEMS, H1D, FDIM);
    ln_relu<H1D><<<NITEMS, 128>>>(t1, gm1, be1);
    sgemm_f32x2<<<dim3(1, MROWS), 256>>>(t1, W2, b2, t2, NITEMS, HID, H1D);
    ln_relu<HID><<<NITEMS, 128>>>(t2, gm2, be2);
    sgemm_f32x2<<<dim3(1, MROWS), 256>>>(t2, W3, b3, t3, NITEMS, HID, HID);

    // ---- fuse metadata + init out ----
    build_e0<<<NNODES, 128>>>(emb, mw, out);

    // ---- degree, dinv, CSR build ----
    zero_deg_cur<<<(NNODES + 255) / 256, 256>>>();
    deg_count<<<(NEDGE + 255) / 256, 256>>>(dst);
    dinv_k<<<(NNODES + 255) / 256, 256>>>();
    scan1<<<SCAN_G, SCAN_B>>>();
    scan2<<<1, 256>>>();
    scan3<<<(NNODES + 255) / 256, 256>>>();
    scatter_edges<<<(NEDGE + 255) / 256, 256>>>(src, dst);

    // ---- 3 propagation layers ----
    float* xin = xa;
    float* xout = xb;
    const int prop_blocks = (int)(((size_t)NNODES * 32 + 255) / 256);
    for (int l = 0; l < 3; ++l) {
        propagate_csr<<<prop_blocks, 256>>>(xin, xout, out);
        float* tmp = xin; xin = xout; xout = tmp;
    }
}

// round 12
// speedup vs baseline: 1.0490x; 1.0490x over previous
#include <cuda_runtime.h>
#include <math.h>
#include <stdint.h>
#include <mma.h>

using namespace nvcuda;

#define NUSERS 50000
#define NITEMS 20000
#define NNODES 70000
#define FDIM   768
#define H1D    512
#define HID    128
#define NEDGE  2000000
#define ALPHA  0.25f
#define LN_EPS 1e-5f

#define SCAN_B 512
#define SCAN_G ((NNODES + SCAN_B - 1) / SCAN_B)   // 137

// ---------------- scratch ----------------
__device__ float g_t1[(size_t)NITEMS * H1D];
__device__ float g_t2[(size_t)NITEMS * HID];
__device__ float g_t3[(size_t)NITEMS * HID];
__device__ float g_xa[(size_t)NNODES * HID];
__device__ float g_xb[(size_t)NNODES * HID];
__device__ float g_dinv[NNODES];
__device__ int   g_deg[NNODES];
__device__ int   g_cur[NNODES];
__device__ int   g_offs[NNODES + 1];
__device__ int   g_bsum[SCAN_G];
__device__ int   g_boff[SCAN_G];
__device__ int   g_csrc[NEDGE];
__device__ float g_cw[NEDGE];

// ---------------- wmma tf32 GEMM: C = A[M,K]@B[K,N] + bias ------------------
// Block tile 128x128, BK=16, 256 threads = 8 warps (4M x 2N), warp tile 32x64.
// K multiple of 16, N multiple of 128 per grid sizing (N=512 or 128); M guarded.
#define AST 20    // As row stride (floats), %4==0 for wmma ldm
#define BST 132   // Bs row stride (floats), %4==0
#define CST 20    // per-warp epilogue tile stride, %4==0
__global__ __launch_bounds__(256) void gemm_wmma(const float* __restrict__ A,
                                                 const float* __restrict__ B,
                                                 const float* __restrict__ bias,
                                                 float* __restrict__ C,
                                                 int M, int N, int K)
{
    __shared__ float As[128 * AST];        // [m][k] row-major
    __shared__ float Bs[16 * BST];         // [k][n] row-major
    __shared__ float Cst[8 * 16 * CST];    // per-warp 16x16 epilogue tiles

    int tid = threadIdx.x;
    int wid = tid >> 5;
    int warpM = wid >> 1;   // 0..3
    int warpN = wid & 1;    // 0..1
    int row0 = blockIdx.y * 128;
    int col0 = blockIdx.x * 128;

    wmma::fragment<wmma::accumulator, 16, 16, 8, float> cf[2][4];
#pragma unroll
    for (int mt = 0; mt < 2; mt++)
#pragma unroll
        for (int nt = 0; nt < 4; nt++) wmma::fill_fragment(cf[mt][nt], 0.f);

    for (int k0 = 0; k0 < K; k0 += 16) {
        // stage A: 128 rows x 16 k (guarded rows -> zeros)
#pragma unroll
        for (int it = 0; it < 2; ++it) {
            int idx = tid + it * 256;              // 0..511
            int r = idx >> 2, c = (idx & 3) * 4;
            int gr = row0 + r;
            float4 v = make_float4(0.f, 0.f, 0.f, 0.f);
            if (gr < M) v = *(const float4*)(A + (size_t)gr * K + k0 + c);
            *(float4*)&As[r * AST + c] = v;
            // stage B: 16 k x 128 n
            int kk = idx >> 5, nc = (idx & 31) * 4;
            float4 bv = *(const float4*)(B + (size_t)(k0 + kk) * N + col0 + nc);
            *(float4*)&Bs[kk * BST + nc] = bv;
        }
        __syncthreads();

#pragma unroll
        for (int kf = 0; kf < 2; kf++) {
            int k = kf * 8;
            wmma::fragment<wmma::matrix_a, 16, 16, 8, wmma::precision::tf32,
                           wmma::row_major> af[2];
            wmma::fragment<wmma::matrix_b, 16, 16, 8, wmma::precision::tf32,
                           wmma::row_major> bf[4];
#pragma unroll
            for (int mt = 0; mt < 2; mt++) {
                wmma::load_matrix_sync(af[mt],
                    &As[(warpM * 32 + mt * 16) * AST + k], AST);
#pragma unroll
                for (int i = 0; i < af[mt].num_elements; i++)
                    af[mt].x[i] = wmma::__float_to_tf32(af[mt].x[i]);
            }
#pragma unroll
            for (int nt = 0; nt < 4; nt++) {
                wmma::load_matrix_sync(bf[nt],
                    &Bs[k * BST + warpN * 64 + nt * 16], BST);
#pragma unroll
                for (int i = 0; i < bf[nt].num_elements; i++)
                    bf[nt].x[i] = wmma::__float_to_tf32(bf[nt].x[i]);
            }
#pragma unroll
            for (int mt = 0; mt < 2; mt++)
#pragma unroll
                for (int nt = 0; nt < 4; nt++)
                    wmma::mma_sync(cf[mt][nt], af[mt], bf[nt], cf[mt][nt]);
        }
        __syncthreads();
    }

    // epilogue: per-warp 16x16 staging, guarded rows, += bias
    float* ct = &Cst[wid * 16 * CST];
    int lane = tid & 31;
    int er = lane >> 1;           // 0..15
    int eh = (lane & 1) * 8;      // 0 or 8
#pragma unroll
    for (int mt = 0; mt < 2; mt++) {
#pragma unroll
        for (int nt = 0; nt < 4; nt++) {
            wmma::store_matrix_sync(ct, cf[mt][nt], CST, wmma::mem_row_major);
            __syncwarp();
            int gr = row0 + warpM * 32 + mt * 16 + er;
            int gc = col0 + warpN * 64 + nt * 16 + eh;
            if (gr < M) {
                float4 p0 = *(float4*)&ct[er * CST + eh];
                float4 p1 = *(float4*)&ct[er * CST + eh + 4];
                p0.x += bias[gc + 0]; p0.y += bias[gc + 1];
                p0.z += bias[gc + 2]; p0.w += bias[gc + 3];
                p1.x += bias[gc + 4]; p1.y += bias[gc + 5];
                p1.z += bias[gc + 6]; p1.w += bias[gc + 7];
                *(float4*)(C + (size_t)gr * N + gc) = p0;
                *(float4*)(C + (size_t)gr * N + gc + 4) = p1;
            }
            __syncwarp();
        }
    }
}

// ---------------- LayerNorm + ReLU ----------------
template <int W>
__global__ void ln_relu(float* __restrict__ x, const float* __restrict__ g,
                        const float* __restrict__ be)
{
    constexpr int VPT = W / 128;
    int row = blockIdx.x;
    int tid = threadIdx.x;
    float* xr = x + (size_t)row * W;

    float v[VPT];
    float s = 0.f, s2 = 0.f;
#pragma unroll
    for (int i = 0; i < VPT; i++) {
        v[i] = xr[i * 128 + tid];
        s += v[i]; s2 += v[i] * v[i];
    }
#pragma unroll
    for (int o = 16; o > 0; o >>= 1) {
        s  += __shfl_xor_sync(0xffffffffu, s,  o);
        s2 += __shfl_xor_sync(0xffffffffu, s2, o);
    }
    __shared__ float rs[4], rs2[4];
    if ((tid & 31) == 0) { rs[tid >> 5] = s; rs2[tid >> 5] = s2; }
    __syncthreads();
    s  = rs[0] + rs[1] + rs[2] + rs[3];
    s2 = rs2[0] + rs2[1] + rs2[2] + rs2[3];

    float mu  = s / W;
    float var = s2 / W - mu * mu;
    float inv = rsqrtf(var + LN_EPS);
#pragma unroll
    for (int i = 0; i < VPT; i++) {
        int c = i * 128 + tid;
        float y = (v[i] - mu) * inv * g[c] + be[c];
        xr[c] = fmaxf(y, 0.f);
    }
}

// ---------------- build e0 ----------------
__global__ void build_e0(const float* __restrict__ emb, const float* __restrict__ mw,
                         float* __restrict__ out)
{
    int node = blockIdx.x;
    int tid = threadIdx.x;   // 128
    float x = emb[(size_t)node * HID + tid];
    if (node >= NUSERS) {
        int it = node - NUSERS;
        float h = g_t3[(size_t)it * HID + tid];
        float s2 = h * h;
#pragma unroll
        for (int o = 16; o > 0; o >>= 1) s2 += __shfl_xor_sync(0xffffffffu, s2, o);
        __shared__ float red[4];
        if ((tid & 31) == 0) red[tid >> 5] = s2;
        __syncthreads();
        float nrm = sqrtf(red[0] + red[1] + red[2] + red[3]);
        x += mw[0] * h / fmaxf(nrm, 1e-12f);
    }
    size_t o = (size_t)node * HID + tid;
    g_xa[o] = x;
    out[o] = ALPHA * x;
}

// ---------------- degree / dinv ----------------
__global__ void zero_deg_cur()
{
    int n = blockIdx.x * blockDim.x + threadIdx.x;
    if (n < NNODES) { g_deg[n] = 0; g_cur[n] = 0; }
}

__global__ void deg_count(const int* __restrict__ dst)
{
    int e = blockIdx.x * blockDim.x + threadIdx.x;
    if (e < NEDGE) atomicAdd(&g_deg[dst[e]], 1);
}

__global__ void dinv_k()
{
    int n = blockIdx.x * blockDim.x + threadIdx.x;
    if (n < NNODES) {
        int d = g_deg[n];
        g_dinv[n] = (d > 0) ? rsqrtf((float)d) : 0.f;
    }
}

// ---------------- exclusive scan of g_deg -> g_offs ----------------
__global__ void scan1()
{
    __shared__ int sm[SCAN_B];
    int i = blockIdx.x * SCAN_B + threadIdx.x;
    int v = (i < NNODES) ? g_deg[i] : 0;
    sm[threadIdx.x] = v;
    __syncthreads();
    int val = v;
#pragma unroll
    for (int o = 1; o < SCAN_B; o <<= 1) {
        int t = (threadIdx.x >= o) ? sm[threadIdx.x - o] : 0;
        __syncthreads();
        val += t;
        sm[threadIdx.x] = val;
        __syncthreads();
    }
    if (i < NNODES) g_offs[i] = val - v;
    if (threadIdx.x == SCAN_B - 1) g_bsum[blockIdx.x] = val;
}

__global__ void scan2()
{
    __shared__ int sm[SCAN_G];
    int t = threadIdx.x;
    int v = (t < SCAN_G) ? g_bsum[t] : 0;
    if (t < SCAN_G) sm[t] = v;
    __syncthreads();
    if (t < SCAN_G) {
        int e = 0;
        for (int j = 0; j < t; j++) e += sm[j];
        g_boff[t] = e;
    }
}

__global__ void scan3()
{
    int i = blockIdx.x * blockDim.x + threadIdx.x;
    if (i < NNODES) g_offs[i] += g_boff[i / SCAN_B];
    if (i == 0) g_offs[NNODES] = NEDGE;
}

// ---------------- scatter edges into CSR (by dst) ----------------
__global__ void scatter_edges(const int* __restrict__ src, const int* __restrict__ dst)
{
    int e = blockIdx.x * blockDim.x + threadIdx.x;
    if (e < NEDGE) {
        int s = src[e];
        int d = dst[e];
        int pos = g_offs[d] + atomicAdd(&g_cur[d], 1);
        g_csrc[pos] = s;
        g_cw[pos] = g_dinv[s];
    }
}

// ---------------- CSR propagate, fused out += alpha * xnew -------------------
__global__ void propagate_csr(const float* __restrict__ xin, float* __restrict__ xout,
                              float* __restrict__ out)
{
    int node = (blockIdx.x * blockDim.x + threadIdx.x) >> 5;
    int lane = threadIdx.x & 31;
    if (node >= NNODES) return;
    int beg = g_offs[node];
    int end = g_offs[node + 1];

    float4 acc = make_float4(0.f, 0.f, 0.f, 0.f);
    int j = beg;
    for (; j + 3 < end; j += 4) {
        int   s0 = __ldg(&g_csrc[j]),     s1 = __ldg(&g_csrc[j + 1]);
        int   s2 = __ldg(&g_csrc[j + 2]), s3 = __ldg(&g_csrc[j + 3]);
        float w0 = __ldg(&g_cw[j]),       w1 = __ldg(&g_cw[j + 1]);
        float w2 = __ldg(&g_cw[j + 2]),   w3 = __ldg(&g_cw[j + 3]);
        float4 v0 = *(const float4*)(xin + (size_t)s0 * HID + lane * 4);
        float4 v1 = *(const float4*)(xin + (size_t)s1 * HID + lane * 4);
        float4 v2 = *(const float4*)(xin + (size_t)s2 * HID + lane * 4);
        float4 v3 = *(const float4*)(xin + (size_t)s3 * HID + lane * 4);
        acc.x += w0 * v0.x + w1 * v1.x + w2 * v2.x + w3 * v3.x;
        acc.y += w0 * v0.y + w1 * v1.y + w2 * v2.y + w3 * v3.y;
        acc.z += w0 * v0.z + w1 * v1.z + w2 * v2.z + w3 * v3.z;
        acc.w += w0 * v0.w + w1 * v1.w + w2 * v2.w + w3 * v3.w;
    }
    for (; j < end; ++j) {
        int   s = __ldg(&g_csrc[j]);
        float w = __ldg(&g_cw[j]);
        float4 v = *(const float4*)(xin + (size_t)s * HID + lane * 4);
        acc.x += w * v.x; acc.y += w * v.y; acc.z += w * v.z; acc.w += w * v.w;
    }

    float dn = g_dinv[node];
    acc.x *= dn; acc.y *= dn; acc.z *= dn; acc.w *= dn;

    size_t o = (size_t)node * HID + lane * 4;
    *(float4*)(xout + o) = acc;
    float4 ov = *(float4*)(out + o);
    ov.x += ALPHA * acc.x; ov.y += ALPHA * acc.y;
    ov.z += ALPHA * acc.z; ov.w += ALPHA * acc.w;
    *(float4*)(out + o) = ov;
}

// ---------------- launch ----------------
extern "C" void kernel_launch(void* const* d_in, const int* in_sizes, int n_in,
                              void* d_out, int out_size)
{
    const int*   eidx = (const int*)d_in[0];
    const float* feat = (const float*)d_in[1];
    const float* emb  = (const float*)d_in[2];
    const float* W1   = (const float*)d_in[3];
    const float* b1   = (const float*)d_in[4];
    const float* gm1  = (const float*)d_in[5];
    const float* be1  = (const float*)d_in[6];
    const float* W2   = (const float*)d_in[7];
    const float* b2   = (const float*)d_in[8];
    const float* gm2  = (const float*)d_in[9];
    const float* be2  = (const float*)d_in[10];
    const float* W3   = (const float*)d_in[11];
    const float* b3   = (const float*)d_in[12];
    const float* mw   = (const float*)d_in[13];
    float* out = (float*)d_out;

    const int* src = eidx;
    const int* dst = eidx + NEDGE;

    float *t1, *t2, *t3, *xa, *xb;
    cudaGetSymbolAddress((void**)&t1, g_t1);
    cudaGetSymbolAddress((void**)&t2, g_t2);
    cudaGetSymbolAddress((void**)&t3, g_t3);
    cudaGetSymbolAddress((void**)&xa, g_xa);
    cudaGetSymbolAddress((void**)&xb, g_xb);

    const int MROWS = (NITEMS + 127) / 128;   // 157

    // ---- item metadata MLP (wmma tf32 tensor-core GEMMs) ----
    gemm_wmma<<<dim3(H1D / 128, MROWS), 256>>>(feat, W1, b1, t1, NITEMS, H1D, FDIM);
    ln_relu<H1D><<<NITEMS, 128>>>(t1, gm1, be1);
    gemm_wmma<<<dim3(1, MROWS), 256>>>(t1, W2, b2, t2, NITEMS, HID, H1D);
    ln_relu<HID><<<NITEMS, 128>>>(t2, gm2, be2);
    gemm_wmma<<<dim3(1, MROWS), 256>>>(t2, W3, b3, t3, NITEMS, HID, HID);

    // ---- fuse metadata + init out ----
    build_e0<<<NNODES, 128>>>(emb, mw, out);

    // ---- degree, dinv, CSR build ----
    zero_deg_cur<<<(NNODES + 255) / 256, 256>>>();
    deg_count<<<(NEDGE + 255) / 256, 256>>>(dst);
    dinv_k<<<(NNODES + 255) / 256, 256>>>();
    scan1<<<SCAN_G, SCAN_B>>>();
    scan2<<<1, 256>>>();
    scan3<<<(NNODES + 255) / 256, 256>>>();
    scatter_edges<<<(NEDGE + 255) / 256, 256>>>(src, dst);

    // ---- 3 propagation layers ----
    float* xin = xa;
    float* xout = xb;
    const int prop_blocks = (int)(((size_t)NNODES * 32 + 255) / 256);
    for (int l = 0; l < 3; ++l) {
        propagate_csr<<<prop_blocks, 256>>>(xin, xout, out);
        float* tmp = xin; xin = xout; xout = tmp;
    }
}

// round 13
// speedup vs baseline: 1.5814x; 1.5075x over previous
#include <cuda_runtime.h>
#include <math.h>
#include <stdint.h>

#define NUSERS 50000
#define NITEMS 20000
#define NNODES 70000
#define FDIM   768
#define H1D    512
#define HID    128
#define NEDGE  2000000
#define ALPHA  0.25f
#define LN_EPS 1e-5f

#define SCAN_B 512
#define SCAN_G ((NNODES + SCAN_B - 1) / SCAN_B)   // 137

// ---------------- scratch ----------------
__device__ float g_t1[(size_t)NITEMS * H1D];
__device__ float g_t2[(size_t)NITEMS * HID];
__device__ float g_t3[(size_t)NITEMS * HID];
__device__ float g_xa[(size_t)NNODES * HID];
__device__ float g_xb[(size_t)NNODES * HID];
__device__ float g_dinv[NNODES];
__device__ int   g_deg[NNODES];
__device__ int   g_cur[NNODES];
__device__ int   g_offs[NNODES + 1];
__device__ int   g_bsum[SCAN_G];
__device__ int   g_boff[SCAN_G];
__device__ int   g_csrc[NEDGE];
__device__ float g_cw[NEDGE];

// ---------------- tf32 helpers ----------------
__device__ __forceinline__ uint32_t f2tf32(float f)
{
    uint32_t u;
    asm("cvt.rna.tf32.f32 %0, %1;" : "=r"(u) : "f"(f));
    return u;
}

__device__ __forceinline__ void mma_tf32(float& c0, float& c1, float& c2, float& c3,
                                         uint32_t a0, uint32_t a1, uint32_t a2, uint32_t a3,
                                         uint32_t b0, uint32_t b1)
{
    asm volatile(
        "mma.sync.aligned.m16n8k8.row.col.f32.tf32.tf32.f32 "
        "{%0,%1,%2,%3}, {%4,%5,%6,%7}, {%8,%9}, {%0,%1,%2,%3};"
        : "+f"(c0), "+f"(c1), "+f"(c2), "+f"(c3)
        : "r"(a0), "r"(a1), "r"(a2), "r"(a3), "r"(b0), "r"(b1));
}

// ---------------- tf32 tensor-core GEMM: C = A[M,K]@B[K,N] + bias ------------
// Block tile 128x128, BK=32, 256 threads = 8 warps (4 M x 2 N), warp tile 32x64.
// tf32 conversion done ONCE at staging; k-major smem; TSTRIDE=136 gives
// lane address pattern qid*8+grp = 0..31 distinct banks -> conflict-free.
#define TSTRIDE 136
__global__ __launch_bounds__(256) void gemm_tf32(const float* __restrict__ A,
                                                 const float* __restrict__ B,
                                                 const float* __restrict__ bias,
                                                 float* __restrict__ C,
                                                 int M, int N, int K)
{
    __shared__ uint32_t As[32 * TSTRIDE];   // As[k][m]
    __shared__ uint32_t Bs[32 * TSTRIDE];   // Bs[k][n]

    int tid = threadIdx.x;
    int wid = tid >> 5;
    int lane = tid & 31;
    int grp = lane >> 2;     // 0..7
    int qid = lane & 3;      // 0..3
    int warpM = wid >> 1;    // 0..3
    int warpN = wid & 1;     // 0..1
    int row0 = blockIdx.y * 128;
    int col0 = blockIdx.x * 128;

    float acc[2][8][4];
#pragma unroll
    for (int mt = 0; mt < 2; mt++)
#pragma unroll
        for (int nt = 0; nt < 8; nt++)
#pragma unroll
            for (int r = 0; r < 4; r++) acc[mt][nt][r] = 0.f;

    for (int k0 = 0; k0 < K; k0 += 32) {
        // stage A (transposed to k-major) with tf32 conversion
#pragma unroll
        for (int i = 0; i < 4; i++) {
            int flat = tid + i * 256;          // 0..1023
            int m = flat >> 3;
            int kc = flat & 7;
            int gr = row0 + m;
            float4 v = make_float4(0.f, 0.f, 0.f, 0.f);
            if (gr < M) v = *(const float4*)(A + (size_t)gr * K + k0 + kc * 4);
            uint32_t* d = &As[(kc * 4) * TSTRIDE + m];
            d[0 * TSTRIDE] = f2tf32(v.x);
            d[1 * TSTRIDE] = f2tf32(v.y);
            d[2 * TSTRIDE] = f2tf32(v.z);
            d[3 * TSTRIDE] = f2tf32(v.w);
        }
        // stage B (k-major already)
#pragma unroll
        for (int i = 0; i < 4; i++) {
            int flat = tid + i * 256;
            int kk = flat >> 5;
            int nc = flat & 31;
            float4 v = *(const float4*)(B + (size_t)(k0 + kk) * N + col0 + nc * 4);
            uint32_t* d = &Bs[kk * TSTRIDE + nc * 4];
            d[0] = f2tf32(v.x); d[1] = f2tf32(v.y);
            d[2] = f2tf32(v.z); d[3] = f2tf32(v.w);
        }
        __syncthreads();

#pragma unroll
        for (int ks = 0; ks < 4; ks++) {
            int k = ks * 8;
            uint32_t a[2][4], b[8][2];
#pragma unroll
            for (int mt = 0; mt < 2; mt++) {
                int mrow = warpM * 32 + mt * 16 + grp;
                a[mt][0] = As[(k + qid) * TSTRIDE + mrow];
                a[mt][1] = As[(k + qid) * TSTRIDE + mrow + 8];
                a[mt][2] = As[(k + qid + 4) * TSTRIDE + mrow];
                a[mt][3] = As[(k + qid + 4) * TSTRIDE + mrow + 8];
            }
#pragma unroll
            for (int nt = 0; nt < 8; nt++) {
                int ncol = warpN * 64 + nt * 8 + grp;
                b[nt][0] = Bs[(k + qid) * TSTRIDE + ncol];
                b[nt][1] = Bs[(k + qid + 4) * TSTRIDE + ncol];
            }
#pragma unroll
            for (int mt = 0; mt < 2; mt++)
#pragma unroll
                for (int nt = 0; nt < 8; nt++)
                    mma_tf32(acc[mt][nt][0], acc[mt][nt][1],
                             acc[mt][nt][2], acc[mt][nt][3],
                             a[mt][0], a[mt][1], a[mt][2], a[mt][3],
                             b[nt][0], b[nt][1]);
        }
        __syncthreads();
    }

    // epilogue: += bias, guarded rows
#pragma unroll
    for (int mt = 0; mt < 2; mt++) {
        int r0 = row0 + warpM * 32 + mt * 16 + grp;
        int r1 = r0 + 8;
#pragma unroll
        for (int nt = 0; nt < 8; nt++) {
            int c = col0 + warpN * 64 + nt * 8 + qid * 2;
            float bx = bias[c], by = bias[c + 1];
            if (r0 < M) {
                float2 v = make_float2(acc[mt][nt][0] + bx, acc[mt][nt][1] + by);
                *(float2*)(C + (size_t)r0 * N + c) = v;
            }
            if (r1 < M) {
                float2 v = make_float2(acc[mt][nt][2] + bx, acc[mt][nt][3] + by);
                *(float2*)(C + (size_t)r1 * N + c) = v;
            }
        }
    }
}

// ---------------- LayerNorm + ReLU ----------------
template <int W>
__global__ void ln_relu(float* __restrict__ x, const float* __restrict__ g,
                        const float* __restrict__ be)
{
    constexpr int VPT = W / 128;
    int row = blockIdx.x;
    int tid = threadIdx.x;
    float* xr = x + (size_t)row * W;

    float v[VPT];
    float s = 0.f, s2 = 0.f;
#pragma unroll
    for (int i = 0; i < VPT; i++) {
        v[i] = xr[i * 128 + tid];
        s += v[i]; s2 += v[i] * v[i];
    }
#pragma unroll
    for (int o = 16; o > 0; o >>= 1) {
        s  += __shfl_xor_sync(0xffffffffu, s,  o);
        s2 += __shfl_xor_sync(0xffffffffu, s2, o);
    }
    __shared__ float rs[4], rs2[4];
    if ((tid & 31) == 0) { rs[tid >> 5] = s; rs2[tid >> 5] = s2; }
    __syncthreads();
    s  = rs[0] + rs[1] + rs[2] + rs[3];
    s2 = rs2[0] + rs2[1] + rs2[2] + rs2[3];

    float mu  = s / W;
    float var = s2 / W - mu * mu;
    float inv = rsqrtf(var + LN_EPS);
#pragma unroll
    for (int i = 0; i < VPT; i++) {
        int c = i * 128 + tid;
        float y = (v[i] - mu) * inv * g[c] + be[c];
        xr[c] = fmaxf(y, 0.f);
    }
}

// ---------------- build e0 ----------------
__global__ void build_e0(const float* __restrict__ emb, const float* __restrict__ mw,
                         float* __restrict__ out)
{
    int node = blockIdx.x;
    int tid = threadIdx.x;   // 128
    float x = emb[(size_t)node * HID + tid];
    if (node >= NUSERS) {
        int it = node - NUSERS;
        float h = g_t3[(size_t)it * HID + tid];
        float s2 = h * h;
#pragma unroll
        for (int o = 16; o > 0; o >>= 1) s2 += __shfl_xor_sync(0xffffffffu, s2, o);
        __shared__ float red[4];
        if ((tid & 31) == 0) red[tid >> 5] = s2;
        __syncthreads();
        float nrm = sqrtf(red[0] + red[1] + red[2] + red[3]);
        x += mw[0] * h / fmaxf(nrm, 1e-12f);
    }
    size_t o = (size_t)node * HID + tid;
    g_xa[o] = x;
    out[o] = ALPHA * x;
}

// ---------------- degree / dinv ----------------
__global__ void zero_deg_cur()
{
    int n = blockIdx.x * blockDim.x + threadIdx.x;
    if (n < NNODES) { g_deg[n] = 0; g_cur[n] = 0; }
}

__global__ void deg_count(const int* __restrict__ dst)
{
    int e = blockIdx.x * blockDim.x + threadIdx.x;
    if (e < NEDGE) atomicAdd(&g_deg[dst[e]], 1);
}

__global__ void dinv_k()
{
    int n = blockIdx.x * blockDim.x + threadIdx.x;
    if (n < NNODES) {
        int d = g_deg[n];
        g_dinv[n] = (d > 0) ? rsqrtf((float)d) : 0.f;
    }
}

// ---------------- exclusive scan of g_deg -> g_offs ----------------
__global__ void scan1()
{
    __shared__ int sm[SCAN_B];
    int i = blockIdx.x * SCAN_B + threadIdx.x;
    int v = (i < NNODES) ? g_deg[i] : 0;
    sm[threadIdx.x] = v;
    __syncthreads();
    int val = v;
#pragma unroll
    for (int o = 1; o < SCAN_B; o <<= 1) {
        int t = (threadIdx.x >= o) ? sm[threadIdx.x - o] : 0;
        __syncthreads();
        val += t;
        sm[threadIdx.x] = val;
        __syncthreads();
    }
    if (i < NNODES) g_offs[i] = val - v;
    if (threadIdx.x == SCAN_B - 1) g_bsum[blockIdx.x] = val;
}

__global__ void scan2()
{
    __shared__ int sm[SCAN_G];
    int t = threadIdx.x;
    int v = (t < SCAN_G) ? g_bsum[t] : 0;
    if (t < SCAN_G) sm[t] = v;
    __syncthreads();
    if (t < SCAN_G) {
        int e = 0;
        for (int j = 0; j < t; j++) e += sm[j];
        g_boff[t] = e;
    }
}

__global__ void scan3()
{
    int i = blockIdx.x * blockDim.x + threadIdx.x;
    if (i < NNODES) g_offs[i] += g_boff[i / SCAN_B];
    if (i == 0) g_offs[NNODES] = NEDGE;
}

// ---------------- scatter edges into CSR (by dst) ----------------
__global__ void scatter_edges(const int* __restrict__ src, const int* __restrict__ dst)
{
    int e = blockIdx.x * blockDim.x + threadIdx.x;
    if (e < NEDGE) {
        int s = src[e];
        int d = dst[e];
        int pos = g_offs[d] + atomicAdd(&g_cur[d], 1);
        g_csrc[pos] = s;
        g_cw[pos] = g_dinv[s];
    }
}

// ---------------- CSR propagate, fused out += alpha * xnew -------------------
__global__ void propagate_csr(const float* __restrict__ xin, float* __restrict__ xout,
                              float* __restrict__ out)
{
    int node = (blockIdx.x * blockDim.x + threadIdx.x) >> 5;
    int lane = threadIdx.x & 31;
    if (node >= NNODES) return;
    int beg = g_offs[node];
    int end = g_offs[node + 1];

    float4 acc = make_float4(0.f, 0.f, 0.f, 0.f);
    int j = beg;
    for (; j + 3 < end; j += 4) {
        int   s0 = __ldg(&g_csrc[j]),     s1 = __ldg(&g_csrc[j + 1]);
        int   s2 = __ldg(&g_csrc[j + 2]), s3 = __ldg(&g_csrc[j + 3]);
        float w0 = __ldg(&g_cw[j]),       w1 = __ldg(&g_cw[j + 1]);
        float w2 = __ldg(&g_cw[j + 2]),   w3 = __ldg(&g_cw[j + 3]);
        float4 v0 = *(const float4*)(xin + (size_t)s0 * HID + lane * 4);
        float4 v1 = *(const float4*)(xin + (size_t)s1 * HID + lane * 4);
        float4 v2 = *(const float4*)(xin + (size_t)s2 * HID + lane * 4);
        float4 v3 = *(const float4*)(xin + (size_t)s3 * HID + lane * 4);
        acc.x += w0 * v0.x + w1 * v1.x + w2 * v2.x + w3 * v3.x;
        acc.y += w0 * v0.y + w1 * v1.y + w2 * v2.y + w3 * v3.y;
        acc.z += w0 * v0.z + w1 * v1.z + w2 * v2.z + w3 * v3.z;
        acc.w += w0 * v0.w + w1 * v1.w + w2 * v2.w + w3 * v3.w;
    }
    for (; j < end; ++j) {
        int   s = __ldg(&g_csrc[j]);
        float w = __ldg(&g_cw[j]);
        float4 v = *(const float4*)(xin + (size_t)s * HID + lane * 4);
        acc.x += w * v.x; acc.y += w * v.y; acc.z += w * v.z; acc.w += w * v.w;
    }

    float dn = g_dinv[node];
    acc.x *= dn; acc.y *= dn; acc.z *= dn; acc.w *= dn;

    size_t o = (size_t)node * HID + lane * 4;
    *(float4*)(xout + o) = acc;
    float4 ov = *(float4*)(out + o);
    ov.x += ALPHA * acc.x; ov.y += ALPHA * acc.y;
    ov.z += ALPHA * acc.z; ov.w += ALPHA * acc.w;
    *(float4*)(out + o) = ov;
}

// ---------------- launch ----------------
extern "C" void kernel_launch(void* const* d_in, const int* in_sizes, int n_in,
                              void* d_out, int out_size)
{
    const int*   eidx = (const int*)d_in[0];
    const float* feat = (const float*)d_in[1];
    const float* emb  = (const float*)d_in[2];
    const float* W1   = (const float*)d_in[3];
    const float* b1   = (const float*)d_in[4];
    const float* gm1  = (const float*)d_in[5];
    const float* be1  = (const float*)d_in[6];
    const float* W2   = (const float*)d_in[7];
    const float* b2   = (const float*)d_in[8];
    const float* gm2  = (const float*)d_in[9];
    const float* be2  = (const float*)d_in[10];
    const float* W3   = (const float*)d_in[11];
    const float* b3   = (const float*)d_in[12];
    const float* mw   = (const float*)d_in[13];
    float* out = (float*)d_out;

    const int* src = eidx;
    const int* dst = eidx + NEDGE;

    float *t1, *t2, *t3, *xa, *xb;
    cudaGetSymbolAddress((void**)&t1, g_t1);
    cudaGetSymbolAddress((void**)&t2, g_t2);
    cudaGetSymbolAddress((void**)&t3, g_t3);
    cudaGetSymbolAddress((void**)&xa, g_xa);
    cudaGetSymbolAddress((void**)&xb, g_xb);

    const int MROWS = (NITEMS + 127) / 128;   // 157

    // ---- item metadata MLP (hand mma.sync tf32 GEMMs) ----
    gemm_tf32<<<dim3(H1D / 128, MROWS), 256>>>(feat, W1, b1, t1, NITEMS, H1D, FDIM);
    ln_relu<H1D><<<NITEMS, 128>>>(t1, gm1, be1);
    gemm_tf32<<<dim3(1, MROWS), 256>>>(t1, W2, b2, t2, NITEMS, HID, H1D);
    ln_relu<HID><<<NITEMS, 128>>>(t2, gm2, be2);
    gemm_tf32<<<dim3(1, MROWS), 256>>>(t2, W3, b3, t3, NITEMS, HID, HID);

    // ---- fuse metadata + init out ----
    build_e0<<<NNODES, 128>>>(emb, mw, out);

    // ---- degree, dinv, CSR build ----
    zero_deg_cur<<<(NNODES + 255) / 256, 256>>>();
    deg_count<<<(NEDGE + 255) / 256, 256>>>(dst);
    dinv_k<<<(NNODES + 255) / 256, 256>>>();
    scan1<<<SCAN_G, SCAN_B>>>();
    scan2<<<1, 256>>>();
    scan3<<<(NNODES + 255) / 256, 256>>>();
    scatter_edges<<<(NEDGE + 255) / 256, 256>>>(src, dst);

    // ---- 3 propagation layers ----
    float* xin = xa;
    float* xout = xb;
    const int prop_blocks = (int)(((size_t)NNODES * 32 + 255) / 256);
    for (int l = 0; l < 3; ++l) {
        propagate_csr<<<prop_blocks, 256>>>(xin, xout, out);
        float* tmp = xin; xin = xout; xout = tmp;
    }
}

// round 17
// speedup vs baseline: 1.6538x; 1.0458x over previous
#include <cuda_runtime.h>
#include <math.h>
#include <stdint.h>

#define NUSERS 50000
#define NITEMS 20000
#define NNODES 70000
#define FDIM   768
#define H1D    512
#define HID    128
#define NEDGE  2000000
#define ALPHA  0.25f
#define LN_EPS 1e-5f

#define SCAN_B 512
#define SCAN_G ((NNODES + SCAN_B - 1) / SCAN_B)   // 137

// ---------------- scratch ----------------
__device__ float g_t1[(size_t)NITEMS * H1D];
__device__ float g_t2[(size_t)NITEMS * HID];
__device__ float g_t3[(size_t)NITEMS * HID];
__device__ float g_xa[(size_t)NNODES * HID];
__device__ float g_xb[(size_t)NNODES * HID];
__device__ float g_dinv[NNODES];
__device__ int   g_deg[NNODES];
__device__ int   g_cur[NNODES];       // scatter cursor, pre-seeded with offs
__device__ int   g_offs[NNODES + 1];
__device__ int   g_bsum[SCAN_G];
__device__ int   g_boff[SCAN_G];
__device__ int2  g_cpk[NEDGE];        // CSR payload: {src, bits(dinv[src])}

// ---------------- mma helper ----------------
__device__ __forceinline__ void mma_tf32(float& c0, float& c1, float& c2, float& c3,
                                         uint32_t a0, uint32_t a1, uint32_t a2, uint32_t a3,
                                         uint32_t b0, uint32_t b1)
{
    asm volatile(
        "mma.sync.aligned.m16n8k8.row.col.f32.tf32.tf32.f32 "
        "{%0,%1,%2,%3}, {%4,%5,%6,%7}, {%8,%9}, {%0,%1,%2,%3};"
        : "+f"(c0), "+f"(c1), "+f"(c2), "+f"(c3)
        : "r"(a0), "r"(a1), "r"(a2), "r"(a3), "r"(b0), "r"(b1));
}

__device__ __forceinline__ void cp16(void* smem_dst, const void* gsrc)
{
    uint32_t sa = (uint32_t)__cvta_generic_to_shared(smem_dst);
    asm volatile("cp.async.cg.shared.global [%0], [%1], 16;" :: "r"(sa), "l"(gsrc));
}

// ---------------- tf32 tensor-core GEMM, cp.async double-buffered ------------
// Block tile 128x128, BK=32, 256 threads = 8 warps (4M x 2N), warp tile 32x64.
// A staged ROW-major (stride 36: fragment addr = 4*grp+qid+c -> conflict-free),
// B staged k-major (stride 136). Raw fp32 bits fed to HMMA (tf32 = RZ truncation).
#define AST 36
#define BST 136
#define AWRDS (128 * AST)          // 4608
#define BWRDS (32 * BST)           // 4352
#define GSMEM_BYTES ((2 * AWRDS + 2 * BWRDS) * 4)   // 71680

__device__ __forceinline__ void stage_tile(const float* __restrict__ A,
                                           const float* __restrict__ B,
                                           uint32_t* Asb, uint32_t* Bsb,
                                           int row0, int col0, int k0,
                                           int M, int N, int K, int tid)
{
#pragma unroll
    for (int i = 0; i < 4; i++) {
        int flat = tid + i * 256;              // 0..1023
        int m = flat >> 3, ko = (flat & 7) * 4;
        int gr = row0 + m;
        if (gr >= M) gr = M - 1;               // garbage rows never stored
        cp16(&Asb[m * AST + ko], A + (size_t)gr * K + k0 + ko);
    }
#pragma unroll
    for (int i = 0; i < 4; i++) {
        int flat = tid + i * 256;
        int kk = flat >> 5, nc = (flat & 31) * 4;
        cp16(&Bsb[kk * BST + nc], B + (size_t)(k0 + kk) * N + col0 + nc);
    }
    asm volatile("cp.async.commit_group;" ::: "memory");
}

__global__ __launch_bounds__(256) void gemm_tf32(const float* __restrict__ A,
                                                 const float* __restrict__ B,
                                                 const float* __restrict__ bias,
                                                 float* __restrict__ C,
                                                 int M, int N, int K)
{
    extern __shared__ uint32_t sh[];
    uint32_t* Asb[2] = { sh, sh + AWRDS };
    uint32_t* Bsb[2] = { sh + 2 * AWRDS, sh + 2 * AWRDS + BWRDS };

    int tid = threadIdx.x;
    int wid = tid >> 5;
    int lane = tid & 31;
    int grp = lane >> 2;     // 0..7
    int qid = lane & 3;      // 0..3
    int warpM = wid >> 1;    // 0..3
    int warpN = wid & 1;     // 0..1
    int row0 = blockIdx.y * 128;
    int col0 = blockIdx.x * 128;

    float acc[2][8][4];
#pragma unroll
    for (int mt = 0; mt < 2; mt++)
#pragma unroll
        for (int nt = 0; nt < 8; nt++)
#pragma unroll
            for (int r = 0; r < 4; r++) acc[mt][nt][r] = 0.f;

    int T = K / 32;
    stage_tile(A, B, Asb[0], Bsb[0], row0, col0, 0, M, N, K, tid);

    for (int t = 0; t < T; t++) {
        if (t + 1 < T) {
            stage_tile(A, B, Asb[(t + 1) & 1], Bsb[(t + 1) & 1],
                       row0, col0, (t + 1) * 32, M, N, K, tid);
            asm volatile("cp.async.wait_group 1;" ::: "memory");
        } else {
            asm volatile("cp.async.wait_group 0;" ::: "memory");
        }
        __syncthreads();

        const uint32_t* Ac = Asb[t & 1];
        const uint32_t* Bc = Bsb[t & 1];
#pragma unroll
        for (int ks = 0; ks < 4; ks++) {
            int k = ks * 8;
            uint32_t a[2][4], b[8][2];
#pragma unroll
            for (int mt = 0; mt < 2; mt++) {
                int mrow = warpM * 32 + mt * 16 + grp;
                a[mt][0] = Ac[mrow * AST + k + qid];
                a[mt][1] = Ac[(mrow + 8) * AST + k + qid];
                a[mt][2] = Ac[mrow * AST + k + qid + 4];
                a[mt][3] = Ac[(mrow + 8) * AST + k + qid + 4];
            }
#pragma unroll
            for (int nt = 0; nt < 8; nt++) {
                int ncol = warpN * 64 + nt * 8 + grp;
                b[nt][0] = Bc[(k + qid) * BST + ncol];
                b[nt][1] = Bc[(k + qid + 4) * BST + ncol];
            }
#pragma unroll
            for (int mt = 0; mt < 2; mt++)
#pragma unroll
                for (int nt = 0; nt < 8; nt++)
                    mma_tf32(acc[mt][nt][0], acc[mt][nt][1],
                             acc[mt][nt][2], acc[mt][nt][3],
                             a[mt][0], a[mt][1], a[mt][2], a[mt][3],
                             b[nt][0], b[nt][1]);
        }
        __syncthreads();
    }

    // epilogue: += bias, guarded rows
#pragma unroll
    for (int mt = 0; mt < 2; mt++) {
        int r0 = row0 + warpM * 32 + mt * 16 + grp;
        int r1 = r0 + 8;
#pragma unroll
        for (int nt = 0; nt < 8; nt++) {
            int c = col0 + warpN * 64 + nt * 8 + qid * 2;
            float bx = bias[c], by = bias[c + 1];
            if (r0 < M) {
                float2 v = make_float2(acc[mt][nt][0] + bx, acc[mt][nt][1] + by);
                *(float2*)(C + (size_t)r0 * N + c) = v;
            }
            if (r1 < M) {
                float2 v = make_float2(acc[mt][nt][2] + bx, acc[mt][nt][3] + by);
                *(float2*)(C + (size_t)r1 * N + c) = v;
            }
        }
    }
}

// ---------------- LayerNorm + ReLU ----------------
template <int W>
__global__ void ln_relu(float* __restrict__ x, const float* __restrict__ g,
                        const float* __restrict__ be)
{
    constexpr int VPT = W / 128;
    int row = blockIdx.x;
    int tid = threadIdx.x;
    float* xr = x + (size_t)row * W;

    float v[VPT];
    float s = 0.f, s2 = 0.f;
#pragma unroll
    for (int i = 0; i < VPT; i++) {
        v[i] = xr[i * 128 + tid];
        s += v[i]; s2 += v[i] * v[i];
    }
#pragma unroll
    for (int o = 16; o > 0; o >>= 1) {
        s  += __shfl_xor_sync(0xffffffffu, s,  o);
        s2 += __shfl_xor_sync(0xffffffffu, s2, o);
    }
    __shared__ float rs[4], rs2[4];
    if ((tid & 31) == 0) { rs[tid >> 5] = s; rs2[tid >> 5] = s2; }
    __syncthreads();
    s  = rs[0] + rs[1] + rs[2] + rs[3];
    s2 = rs2[0] + rs2[1] + rs2[2] + rs2[3];

    float mu  = s / W;
    float var = s2 / W - mu * mu;
    float inv = rsqrtf(var + LN_EPS);
#pragma unroll
    for (int i = 0; i < VPT; i++) {
        int c = i * 128 + tid;
        float y = (v[i] - mu) * inv * g[c] + be[c];
        xr[c] = fmaxf(y, 0.f);
    }
}

// ---------------- build e0 ----------------
__global__ void build_e0(const float* __restrict__ emb, const float* __restrict__ mw,
                         float* __restrict__ out)
{
    int node = blockIdx.x;
    int tid = threadIdx.x;   // 128
    float x = emb[(size_t)node * HID + tid];
    if (node >= NUSERS) {
        int it = node - NUSERS;
        float h = g_t3[(size_t)it * HID + tid];
        float s2 = h * h;
#pragma unroll
        for (int o = 16; o > 0; o >>= 1) s2 += __shfl_xor_sync(0xffffffffu, s2, o);
        __shared__ float red[4];
        if ((tid & 31) == 0) red[tid >> 5] = s2;
        __syncthreads();
        float nrm = sqrtf(red[0] + red[1] + red[2] + red[3]);
        x += mw[0] * h / fmaxf(nrm, 1e-12f);
    }
    size_t o = (size_t)node * HID + tid;
    g_xa[o] = x;
    out[o] = ALPHA * x;
}

// ---------------- degree ----------------
__global__ void zero_deg()
{
    int n = blockIdx.x * blockDim.x + threadIdx.x;
    if (n < NNODES) g_deg[n] = 0;
}

__global__ void deg_count(const int* __restrict__ dst)
{
    int e = blockIdx.x * blockDim.x + threadIdx.x;
    if (e < NEDGE) atomicAdd(&g_deg[dst[e]], 1);
}

// ---------------- scan (+ fused dinv) ----------------
__global__ void scan1()
{
    __shared__ int sm[SCAN_B];
    int i = blockIdx.x * SCAN_B + threadIdx.x;
    int v = (i < NNODES) ? g_deg[i] : 0;
    if (i < NNODES) g_dinv[i] = (v > 0) ? rsqrtf((float)v) : 0.f;
    sm[threadIdx.x] = v;
    __syncthreads();
    int val = v;
#pragma unroll
    for (int o = 1; o < SCAN_B; o <<= 1) {
        int t = (threadIdx.x >= o) ? sm[threadIdx.x - o] : 0;
        __syncthreads();
        val += t;
        sm[threadIdx.x] = val;
        __syncthreads();
    }
    if (i < NNODES) g_offs[i] = val - v;
    if (threadIdx.x == SCAN_B - 1) g_bsum[blockIdx.x] = val;
}

__global__ void scan2()
{
    __shared__ int sm[SCAN_G];
    int t = threadIdx.x;
    int v = (t < SCAN_G) ? g_bsum[t] : 0;
    if (t < SCAN_G) sm[t] = v;
    __syncthreads();
    if (t < SCAN_G) {
        int e = 0;
        for (int j = 0; j < t; j++) e += sm[j];
        g_boff[t] = e;
    }
}

__global__ void scan3()
{
    int i = blockIdx.x * blockDim.x + threadIdx.x;
    if (i < NNODES) {
        int o = g_offs[i] + g_boff[i / SCAN_B];
        g_offs[i] = o;
        g_cur[i] = o;           // seed scatter cursor
    }
    if (i == 0) g_offs[NNODES] = NEDGE;
}

// ---------------- scatter edges into CSR (packed int2) ----------------
__global__ void scatter_edges(const int* __restrict__ src, const int* __restrict__ dst)
{
    int e = blockIdx.x * blockDim.x + threadIdx.x;
    if (e < NEDGE) {
        int s = src[e];
        int d = dst[e];
        int pos = atomicAdd(&g_cur[d], 1);
        g_cpk[pos] = make_int2(s, __float_as_int(g_dinv[s]));
    }
}

// ---------------- CSR propagate, fused out += alpha * xnew -------------------
__global__ void propagate_csr(const float* __restrict__ xin, float* __restrict__ xout,
                              float* __restrict__ out)
{
    int node = (blockIdx.x * blockDim.x + threadIdx.x) >> 5;
    int lane = threadIdx.x & 31;
    if (node >= NNODES) return;
    int beg = g_offs[node];
    int end = g_offs[node + 1];

    float4 acc = make_float4(0.f, 0.f, 0.f, 0.f);
    int j = beg;
    for (; j + 3 < end; j += 4) {
        int2 p0 = __ldg(&g_cpk[j]),     p1 = __ldg(&g_cpk[j + 1]);
        int2 p2 = __ldg(&g_cpk[j + 2]), p3 = __ldg(&g_cpk[j + 3]);
        float w0 = __int_as_float(p0.y), w1 = __int_as_float(p1.y);
        float w2 = __int_as_float(p2.y), w3 = __int_as_float(p3.y);
        float4 v0 = *(const float4*)(xin + (size_t)p0.x * HID + lane * 4);
        float4 v1 = *(const float4*)(xin + (size_t)p1.x * HID + lane * 4);
        float4 v2 = *(const float4*)(xin + (size_t)p2.x * HID + lane * 4);
        float4 v3 = *(const float4*)(xin + (size_t)p3.x * HID + lane * 4);
        acc.x += w0 * v0.x + w1 * v1.x + w2 * v2.x + w3 * v3.x;
        acc.y += w0 * v0.y + w1 * v1.y + w2 * v2.y + w3 * v3.y;
        acc.z += w0 * v0.z + w1 * v1.z + w2 * v2.z + w3 * v3.z;
        acc.w += w0 * v0.w + w1 * v1.w + w2 * v2.w + w3 * v3.w;
    }
    for (; j < end; ++j) {
        int2 p = __ldg(&g_cpk[j]);
        float w = __int_as_float(p.y);
        float4 v = *(const float4*)(xin + (size_t)p.x * HID + lane * 4);
        acc.x += w * v.x; acc.y += w * v.y; acc.z += w * v.z; acc.w += w * v.w;
    }

    float dn = g_dinv[node];
    acc.x *= dn; acc.y *= dn; acc.z *= dn; acc.w *= dn;

    size_t o = (size_t)node * HID + lane * 4;
    *(float4*)(xout + o) = acc;
    float4 ov = *(float4*)(out + o);
    ov.x += ALPHA * acc.x; ov.y += ALPHA * acc.y;
    ov.z += ALPHA * acc.z; ov.w += ALPHA * acc.w;
    *(float4*)(out + o) = ov;
}

// ---------------- launch ----------------
extern "C" void kernel_launch(void* const* d_in, const int* in_sizes, int n_in,
                              void* d_out, int out_size)
{
    const int*   eidx = (const int*)d_in[0];
    const float* feat = (const float*)d_in[1];
    const float* emb  = (const float*)d_in[2];
    const float* W1   = (const float*)d_in[3];
    const float* b1   = (const float*)d_in[4];
    const float* gm1  = (const float*)d_in[5];
    const float* be1  = (const float*)d_in[6];
    const float* W2   = (const float*)d_in[7];
    const float* b2   = (const float*)d_in[8];
    const float* gm2  = (const float*)d_in[9];
    const float* be2  = (const float*)d_in[10];
    const float* W3   = (const float*)d_in[11];
    const float* b3   = (const float*)d_in[12];
    const float* mw   = (const float*)d_in[13];
    float* out = (float*)d_out;

    const int* src = eidx;
    const int* dst = eidx + NEDGE;

    float *t1, *t2, *t3, *xa, *xb;
    cudaGetSymbolAddress((void**)&t1, g_t1);
    cudaGetSymbolAddress((void**)&t2, g_t2);
    cudaGetSymbolAddress((void**)&t3, g_t3);
    cudaGetSymbolAddress((void**)&xa, g_xa);
    cudaGetSymbolAddress((void**)&xb, g_xb);

    cudaFuncSetAttribute(gemm_tf32, cudaFuncAttributeMaxDynamicSharedMemorySize,
                         GSMEM_BYTES);

    const int MROWS = (NITEMS + 127) / 128;   // 157

    // ---- item metadata MLP (tf32 mma, cp.async double-buffered) ----
    gemm_tf32<<<dim3(H1D / 128, MROWS), 256, GSMEM_BYTES>>>(feat, W1, b1, t1,
                                                            NITEMS, H1D, FDIM);
    ln_relu<H1D><<<NITEMS, 128>>>(t1, gm1, be1);
    gemm_tf32<<<dim3(1, MROWS), 256, GSMEM_BYTES>>>(t1, W2, b2, t2,
                                                    NITEMS, HID, H1D);
    ln_relu<HID><<<NITEMS, 128>>>(t2, gm2, be2);
    gemm_tf32<<<dim3(1, MROWS), 256, GSMEM_BYTES>>>(t2, W3, b3, t3,
                                                    NITEMS, HID, HID);

    // ---- fuse metadata + init out ----
    build_e0<<<NNODES, 128>>>(emb, mw, out);

    // ---- degree, dinv, CSR build ----
    zero_deg<<<(NNODES + 255) / 256, 256>>>();
    deg_count<<<(NEDGE + 255) / 256, 256>>>(dst);
    scan1<<<SCAN_G, SCAN_B>>>();
    scan2<<<1, 256>>>();
    scan3<<<(NNODES + 255) / 256, 256>>>();
    scatter_edges<<<(NEDGE + 255) / 256, 256>>>(src, dst);

    // ---- 3 propagation layers ----
    float* xin = xa;
    float* xout = xb;
    const int prop_blocks = (int)(((size_t)NNODES * 32 + 255) / 256);
    for (int l = 0; l < 3; ++l) {
        propagate_csr<<<prop_blocks, 256>>>(xin, xout, out);
        float* tmp = xin; xin = xout; xout = tmp;
    }
}